// round 8
// baseline (speedup 1.0000x reference)
#include <cuda_runtime.h>
#include <cstdint>

// MultiScaleDeformableAttention (bs=8, nq=900, nh=8, d=32, nl=4, npt=4)
// value: (8,22223,8,32) f32 | loc: (8,900,8,4,4,2) f32 | aw: (8,900,8,4,4) f32
// out: (8,900,256) f32
//
// R7: cp.async.ca gather pipeline. Phase 1: per-unit lanes prep offsets+coeffs
// into smem (__syncwarp only). Phase 2: 3-stage cp.async pipeline over points;
// each lane copies its 16B chunk of 4 corners into a smem stage, consumes a
// point after wait_group 2. In-flight lines live in smem, not registers.

#define MSDA_NQ   900
#define MSDA_NH   8
#define MSDA_D    32
#define MSDA_KEYS 22223
#define MSDA_UNITS (8 * MSDA_NQ * MSDA_NH)   // 57600
#define UPB   32                             // units per block
#define DEPTH 3
#define PAD   33
#define STAGE_BYTES (UPB * 4 * 128)          // 16384 per point-stage
#define OFF_BYTES  (16 * PAD * 16)           // 8448
#define SMEM_TOTAL (2 * OFF_BYTES + DEPTH * STAGE_BYTES)   // 66048

typedef unsigned long long u64t;

__device__ __forceinline__ u64t pk2(float a) {
    u64t r; asm("mov.b64 %0, {%1, %1};" : "=l"(r) : "f"(a)); return r;
}
__device__ __forceinline__ void fma2(u64t& d, u64t a, u64t b) {
    asm("fma.rn.f32x2 %0, %1, %2, %0;" : "+l"(d) : "l"(a), "l"(b));
}
__device__ __forceinline__ void cp16(uint32_t saddr, const void* gptr) {
    asm volatile("cp.async.ca.shared.global [%0], [%1], 16;" :: "r"(saddr), "l"(gptr));
}
__device__ __forceinline__ void cpcommit() {
    asm volatile("cp.async.commit_group;");
}
template <int N> __device__ __forceinline__ void cpwait() {
    asm volatile("cp.async.wait_group %0;" :: "n"(N));
}

// Prep one point: absolute byte offsets (incl. level start) + corner coeffs.
__device__ __forceinline__ void prep_point(
    float lx, float ly, float w, int Wd, int Hd, int start_bytes,
    int4* __restrict__ op, float4* __restrict__ cp)
{
    const float x = fmaf(lx, (float)Wd, -0.5f);
    const float y = fmaf(ly, (float)Hd, -0.5f);
    const int x0 = __float2int_rd(x);
    const int y0 = __float2int_rd(y);
    const float wx1 = x - (float)x0, wy1 = y - (float)y0;
    const float wx0 = 1.0f - wx1,    wy0 = 1.0f - wy1;

    const bool vx0 = (unsigned)x0       < (unsigned)Wd;
    const bool vx1 = (unsigned)(x0 + 1) < (unsigned)Wd;
    const bool vy0 = (unsigned)y0       < (unsigned)Hd;
    const bool vy1 = (unsigned)(y0 + 1) < (unsigned)Hd;

    const int x0c = min(max(x0, 0), Wd - 1);
    const int x1c = min(max(x0 + 1, 0), Wd - 1);
    const int y0c = min(max(y0, 0), Hd - 1);
    const int y1c = min(max(y0 + 1, 0), Hd - 1);

    const int r0 = y0c * Wd, r1 = y1c * Wd;
    *op = make_int4(start_bytes + ((r0 + x0c) << 10),
                    start_bytes + ((r0 + x1c) << 10),
                    start_bytes + ((r1 + x0c) << 10),
                    start_bytes + ((r1 + x1c) << 10));

    const float wwy0 = w * wy0, wwy1 = w * wy1;
    *cp = make_float4(vx0 && vy0 ? wx0 * wwy0 : 0.0f,
                      vx1 && vy0 ? wx1 * wwy0 : 0.0f,
                      vx0 && vy1 ? wx0 * wwy1 : 0.0f,
                      vx1 && vy1 ? wx1 * wwy1 : 0.0f);
}

__global__ __launch_bounds__(256) void msda_kernel(
    const float* __restrict__ value,
    const float* __restrict__ loc,
    const float* __restrict__ aw,
    float* __restrict__ out)
{
    extern __shared__ char smem[];
    int4*   off_s = (int4*)smem;                        // [16][PAD]
    float4* cf_s  = (float4*)(smem + OFF_BYTES);        // [16][PAD]
    char*   stage = smem + 2 * OFF_BYTES;               // DEPTH stages

    const int tid = threadIdx.x;
    const int u0  = blockIdx.x * UPB;
    const int lu  = tid >> 3;       // local unit 0..31
    const int j   = tid & 7;        // lane within unit

    // ---- Phase 1: lane j preps points 2j, 2j+1 of its unit ----
    {
        const float4 l2 = __ldg((const float4*)loc + (size_t)u0 * 8 + tid);
        const float2 w2 = __ldg((const float2*)aw  + (size_t)u0 * 8 + tid);

        const int lvl = j >> 1;
        const int Wd = lvl == 0 ? 167 : lvl == 1 ? 84 : lvl == 2 ? 42 : 21;
        const int Hd = lvl == 0 ? 100 : lvl == 1 ? 50 : lvl == 2 ? 25 : 13;
        const int sb = lvl == 0 ? 0
                     : lvl == 1 ? 16700 * 1024
                     : lvl == 2 ? 20900 * 1024
                     :            21950 * 1024;

        prep_point(l2.x, l2.y, w2.x, Wd, Hd, sb,
                   &off_s[(2 * j) * PAD + lu],     &cf_s[(2 * j) * PAD + lu]);
        prep_point(l2.z, l2.w, w2.y, Wd, Hd, sb,
                   &off_s[(2 * j + 1) * PAD + lu], &cf_s[(2 * j + 1) * PAD + lu]);
    }
    __syncwarp();   // producers of this unit's offsets are in the same warp

    // ---- Phase 2: 3-stage cp.async pipeline over the 16 points ----
    const int u  = u0 + lu;
    const int h  = u & 7;
    const int b  = u / (MSDA_NQ * MSDA_NH);

    const char* __restrict__ gbase = (const char*)
        (value + (size_t)b * (MSDA_KEYS * 256) + h * MSDA_D + (j << 2));

    // this thread's smem slot base: stage + lu*512 + j*16  (corner c at +c*128)
    const uint32_t slot0 =
        (uint32_t)__cvta_generic_to_shared(stage) + lu * 512 + j * 16;
    char* const myslot = stage + lu * 512 + j * 16;

    u64t a0 = 0, a1 = 0;

    // prologue: stages for points 0, 1
    #pragma unroll
    for (int p = 0; p < DEPTH - 1; p++) {
        const int4 o = off_s[p * PAD + lu];
        const uint32_t s = slot0 + p * STAGE_BYTES;
        cp16(s,       gbase + o.x);
        cp16(s + 128, gbase + o.y);
        cp16(s + 256, gbase + o.z);
        cp16(s + 384, gbase + o.w);
        cpcommit();
    }

    #pragma unroll
    for (int p = 0; p < 16; p++) {
        // issue point p+DEPTH-1
        if (p + DEPTH - 1 < 16) {
            const int4 o = off_s[(p + DEPTH - 1) * PAD + lu];
            const uint32_t s = slot0 + ((p + DEPTH - 1) % DEPTH) * STAGE_BYTES;
            cp16(s,       gbase + o.x);
            cp16(s + 128, gbase + o.y);
            cp16(s + 256, gbase + o.z);
            cp16(s + 384, gbase + o.w);
        }
        cpcommit();                 // keep group accounting uniform
        cpwait<DEPTH - 1>();        // point p's group complete

        const float4 cf = cf_s[p * PAD + lu];
        const char* sl = myslot + (p % DEPTH) * STAGE_BYTES;
        const ulonglong2 v00 = *(const ulonglong2*)(sl);
        const ulonglong2 v01 = *(const ulonglong2*)(sl + 128);
        const ulonglong2 v10 = *(const ulonglong2*)(sl + 256);
        const ulonglong2 v11 = *(const ulonglong2*)(sl + 384);

        const u64t p00 = pk2(cf.x), p01 = pk2(cf.y);
        const u64t p10 = pk2(cf.z), p11 = pk2(cf.w);
        fma2(a0, p00, v00.x);  fma2(a1, p00, v00.y);
        fma2(a0, p01, v01.x);  fma2(a1, p01, v01.y);
        fma2(a0, p10, v10.x);  fma2(a1, p10, v10.y);
        fma2(a0, p11, v11.x);  fma2(a1, p11, v11.y);
    }

    float f0, f1, f2, f3;
    asm("mov.b64 {%0, %1}, %2;" : "=f"(f0), "=f"(f1) : "l"(a0));
    asm("mov.b64 {%0, %1}, %2;" : "=f"(f2), "=f"(f3) : "l"(a1));
    *(float4*)(out + (size_t)u * MSDA_D + (j << 2)) = make_float4(f0, f1, f2, f3);
}

extern "C" void kernel_launch(void* const* d_in, const int* in_sizes, int n_in,
                              void* d_out, int out_size)
{
    const float* value = (const float*)d_in[0];
    const float* locp  = (const float*)d_in[1];
    const float* aw    = (const float*)d_in[2];
    float* out = (float*)d_out;

    static int attr_done = 0;
    cudaFuncSetAttribute(msda_kernel,
                         cudaFuncAttributeMaxDynamicSharedMemorySize, SMEM_TOTAL);
    (void)attr_done;

    const int blocks = MSDA_UNITS / UPB;   // 1800, exact
    msda_kernel<<<blocks, 256, SMEM_TOTAL>>>(value, locp, aw, out);
}

// round 10
// speedup vs baseline: 1.1410x; 1.1410x over previous
#include <cuda_runtime.h>
#include <cstdint>

// MultiScaleDeformableAttention (bs=8, nq=900, nh=8, d=32, nl=4, npt=4)
// value: (8,22223,8,32) f32 | loc: (8,900,8,4,4,2) f32 | aw: (8,900,8,4,4) f32
// out: (8,900,256) f32
//
// R8: LDG.64 geometry. 16 lanes per (b,q,h) unit (8B channel chunk each),
// 2 units per warp, 16 units per block. Phase 1: each lane preps exactly one
// point (offsets+coeffs -> smem, __syncwarp). Phase 2: points in pairs,
// 8 x LDG.64 in flight (16 data regs), packed f32x2 FMAs.
// Lines-in-flight/SM ~= 40 warps x 16 = 640 (vs ~240 in R6).

#define MSDA_NQ   900
#define MSDA_NH   8
#define MSDA_D    32
#define MSDA_KEYS 22223
#define MSDA_UNITS (8 * MSDA_NQ * MSDA_NH)   // 57600
#define UPB 16                               // units per block
#define PADU 17                              // padded unit stride in smem

typedef unsigned long long u64t;

__device__ __forceinline__ u64t pk2(float a) {
    u64t r; asm("mov.b64 %0, {%1, %1};" : "=l"(r) : "f"(a)); return r;
}
__device__ __forceinline__ void fma2(u64t& d, u64t a, u64t b) {
    asm("fma.rn.f32x2 %0, %1, %2, %0;" : "+l"(d) : "l"(a), "l"(b));
}
__device__ __forceinline__ void add2(u64t& d, u64t a) {
    asm("add.rn.f32x2 %0, %0, %1;" : "+l"(d) : "l"(a));
}
__device__ __forceinline__ u64t ldg64(const char* base, int byte_off) {
    return __ldg((const u64t*)(base + byte_off));
}

// Prep one point: absolute byte offsets (incl. level start) + corner coeffs.
__device__ __forceinline__ void prep_point(
    float lx, float ly, float w, int Wd, int Hd, int start_bytes,
    int4* __restrict__ op, float4* __restrict__ cp)
{
    const float x = fmaf(lx, (float)Wd, -0.5f);
    const float y = fmaf(ly, (float)Hd, -0.5f);
    const int x0 = __float2int_rd(x);
    const int y0 = __float2int_rd(y);
    const float wx1 = x - (float)x0, wy1 = y - (float)y0;
    const float wx0 = 1.0f - wx1,    wy0 = 1.0f - wy1;

    const bool vx0 = (unsigned)x0       < (unsigned)Wd;
    const bool vx1 = (unsigned)(x0 + 1) < (unsigned)Wd;
    const bool vy0 = (unsigned)y0       < (unsigned)Hd;
    const bool vy1 = (unsigned)(y0 + 1) < (unsigned)Hd;

    const int x0c = min(max(x0, 0), Wd - 1);
    const int x1c = min(max(x0 + 1, 0), Wd - 1);
    const int y0c = min(max(y0, 0), Hd - 1);
    const int y1c = min(max(y0 + 1, 0), Hd - 1);

    const int r0 = y0c * Wd, r1 = y1c * Wd;
    // key stride = 256 floats = 1024 bytes
    *op = make_int4(start_bytes + ((r0 + x0c) << 10),
                    start_bytes + ((r0 + x1c) << 10),
                    start_bytes + ((r1 + x0c) << 10),
                    start_bytes + ((r1 + x1c) << 10));

    const float wwy0 = w * wy0, wwy1 = w * wy1;
    *cp = make_float4(vx0 && vy0 ? wx0 * wwy0 : 0.0f,
                      vx1 && vy0 ? wx1 * wwy0 : 0.0f,
                      vx0 && vy1 ? wx0 * wwy1 : 0.0f,
                      vx1 && vy1 ? wx1 * wwy1 : 0.0f);
}

__global__ __launch_bounds__(256, 5) void msda_kernel(
    const float* __restrict__ value,
    const float* __restrict__ loc,
    const float* __restrict__ aw,
    float* __restrict__ out)
{
    // point-major: iter p reads [p][lu] (broadcast within each 16-lane group)
    __shared__ int4   off_s[16][PADU];
    __shared__ float4 cf_s [16][PADU];

    const int tid = threadIdx.x;
    const int u0  = blockIdx.x * UPB;
    const int lu  = tid >> 4;       // local unit 0..15
    const int j   = tid & 15;       // lane within unit = point id (phase 1)
                                    //                  = channel chunk (phase 2)

    // ---- Phase 1: lane j preps point j of its unit ----
    {
        const float2 l = __ldg((const float2*)loc + (size_t)u0 * 16 + tid);
        const float  w = __ldg(aw + (size_t)u0 * 16 + tid);

        const int lvl = j >> 2;
        const int Wd = lvl == 0 ? 167 : lvl == 1 ? 84 : lvl == 2 ? 42 : 21;
        const int Hd = lvl == 0 ? 100 : lvl == 1 ? 50 : lvl == 2 ? 25 : 13;
        const int sb = lvl == 0 ? 0
                     : lvl == 1 ? 16700 * 1024
                     : lvl == 2 ? 20900 * 1024
                     :            21950 * 1024;

        prep_point(l.x, l.y, w, Wd, Hd, sb, &off_s[j][lu], &cf_s[j][lu]);
    }
    __syncwarp();   // each unit's 16 producers == its 16 consumers (same warp)

    // ---- Phase 2: gather loop, points in pairs, 8 x LDG.64 in flight ----
    const int u = u0 + lu;
    const int h = u & 7;
    const int b = u / (MSDA_NQ * MSDA_NH);

    const char* __restrict__ gbase = (const char*)
        (value + (size_t)b * (MSDA_KEYS * 256) + h * MSDA_D) + (j << 3);

    u64t accA = 0, accB = 0;

    #pragma unroll
    for (int p = 0; p < 16; p += 2) {
        const int4   oA = off_s[p][lu];
        const float4 cA = cf_s [p][lu];
        const int4   oB = off_s[p + 1][lu];
        const float4 cB = cf_s [p + 1][lu];

        // 8 independent 64-bit gathers in flight (16 lines/warp across 2 units)
        const u64t vA00 = ldg64(gbase, oA.x);
        const u64t vA01 = ldg64(gbase, oA.y);
        const u64t vA10 = ldg64(gbase, oA.z);
        const u64t vA11 = ldg64(gbase, oA.w);
        const u64t vB00 = ldg64(gbase, oB.x);
        const u64t vB01 = ldg64(gbase, oB.y);
        const u64t vB10 = ldg64(gbase, oB.z);
        const u64t vB11 = ldg64(gbase, oB.w);

        fma2(accA, pk2(cA.x), vA00);
        fma2(accA, pk2(cA.y), vA01);
        fma2(accA, pk2(cA.z), vA10);
        fma2(accA, pk2(cA.w), vA11);
        fma2(accB, pk2(cB.x), vB00);
        fma2(accB, pk2(cB.y), vB01);
        fma2(accB, pk2(cB.z), vB10);
        fma2(accB, pk2(cB.w), vB11);
    }

    add2(accA, accB);

    float f0, f1;
    asm("mov.b64 {%0, %1}, %2;" : "=f"(f0), "=f"(f1) : "l"(accA));
    // 16 lanes x 8B = one contiguous 128B line per unit
    *(float2*)(out + (size_t)u * MSDA_D + (j << 1)) = make_float2(f0, f1);
}

extern "C" void kernel_launch(void* const* d_in, const int* in_sizes, int n_in,
                              void* d_out, int out_size)
{
    const float* value = (const float*)d_in[0];
    const float* locp  = (const float*)d_in[1];
    const float* aw    = (const float*)d_in[2];
    float* out = (float*)d_out;

    const int blocks = MSDA_UNITS / UPB;   // 3600, exact
    msda_kernel<<<blocks, 256>>>(value, locp, aw, out);
}

// round 15
// speedup vs baseline: 1.2888x; 1.1296x over previous
#include <cuda_runtime.h>
#include <cstdint>

// MultiScaleDeformableAttention (bs=8, nq=900, nh=8, d=32, nl=4, npt=4)
// value: (8,22223,8,32) f32 | loc: (8,900,8,4,4,2) f32 | aw: (8,900,8,4,4) f32
// out: (8,900,256) f32
//
// R9: warp-per-unit, lane-per-channel, LDG.32 gathers. Every corner load is
// a single 128B line shared by all 32 lanes -> one L1tex wavefront per LDG
// at cross-LDG rate (no within-LDG replays). In-flight corner costs 1 reg
// per thread -> 32 corner lines in flight per warp (2 halves x 8 points).
// Phase 1: lanes 0-15 prep one point each into smem (__syncwarp only).

#define MSDA_NQ   900
#define MSDA_NH   8
#define MSDA_D    32
#define MSDA_KEYS 22223
#define MSDA_UNITS (8 * MSDA_NQ * MSDA_NH)   // 57600
#define WARPS_PER_BLOCK 8

// Prep one point: absolute byte offsets (incl. level start) + corner coeffs.
__device__ __forceinline__ void prep_point(
    float lx, float ly, float w, int Wd, int Hd, int start_bytes,
    int4* __restrict__ op, float4* __restrict__ cp)
{
    const float x = fmaf(lx, (float)Wd, -0.5f);
    const float y = fmaf(ly, (float)Hd, -0.5f);
    const int x0 = __float2int_rd(x);
    const int y0 = __float2int_rd(y);
    const float wx1 = x - (float)x0, wy1 = y - (float)y0;
    const float wx0 = 1.0f - wx1,    wy0 = 1.0f - wy1;

    const bool vx0 = (unsigned)x0       < (unsigned)Wd;
    const bool vx1 = (unsigned)(x0 + 1) < (unsigned)Wd;
    const bool vy0 = (unsigned)y0       < (unsigned)Hd;
    const bool vy1 = (unsigned)(y0 + 1) < (unsigned)Hd;

    const int x0c = min(max(x0, 0), Wd - 1);
    const int x1c = min(max(x0 + 1, 0), Wd - 1);
    const int y0c = min(max(y0, 0), Hd - 1);
    const int y1c = min(max(y0 + 1, 0), Hd - 1);

    const int r0 = y0c * Wd, r1 = y1c * Wd;
    // key stride = 256 floats = 1024 bytes
    *op = make_int4(start_bytes + ((r0 + x0c) << 10),
                    start_bytes + ((r0 + x1c) << 10),
                    start_bytes + ((r1 + x0c) << 10),
                    start_bytes + ((r1 + x1c) << 10));

    const float wwy0 = w * wy0, wwy1 = w * wy1;
    *cp = make_float4(vx0 && vy0 ? wx0 * wwy0 : 0.0f,
                      vx1 && vy0 ? wx1 * wwy0 : 0.0f,
                      vx0 && vy1 ? wx0 * wwy1 : 0.0f,
                      vx1 && vy1 ? wx1 * wwy1 : 0.0f);
}

__global__ __launch_bounds__(256, 4) void msda_kernel(
    const float* __restrict__ value,
    const float* __restrict__ loc,
    const float* __restrict__ aw,
    float* __restrict__ out)
{
    __shared__ int4   off_s[WARPS_PER_BLOCK][16];
    __shared__ float4 cf_s [WARPS_PER_BLOCK][16];

    const int tid  = threadIdx.x;
    const int wid  = tid >> 5;
    const int lane = tid & 31;
    const int u    = blockIdx.x * WARPS_PER_BLOCK + wid;   // one unit per warp

    // ---- Phase 1: lanes 0..15 prep one point each ----
    if (lane < 16) {
        const float2 l = __ldg((const float2*)loc + (size_t)u * 16 + lane);
        const float  w = __ldg(aw + (size_t)u * 16 + lane);

        const int lvl = lane >> 2;
        const int Wd = lvl == 0 ? 167 : lvl == 1 ? 84 : lvl == 2 ? 42 : 21;
        const int Hd = lvl == 0 ? 100 : lvl == 1 ? 50 : lvl == 2 ? 25 : 13;
        const int sb = lvl == 0 ? 0
                     : lvl == 1 ? 16700 * 1024
                     : lvl == 2 ? 20900 * 1024
                     :            21950 * 1024;

        prep_point(l.x, l.y, w, Wd, Hd, sb, &off_s[wid][lane], &cf_s[wid][lane]);
    }
    __syncwarp();

    // ---- Phase 2: LDG.32 gather, 8 points (32 lines) in flight per half ----
    const int h = u & 7;
    const int b = u / (MSDA_NQ * MSDA_NH);

    const char* __restrict__ gbase = (const char*)
        (value + (size_t)b * (MSDA_KEYS * 256) + h * MSDA_D) + (lane << 2);

    float acc0 = 0.0f, acc1 = 0.0f;

    #pragma unroll
    for (int half = 0; half < 2; half++) {
        float v[8][4];   // 32 in-flight corner values (1 reg each)

        #pragma unroll
        for (int p = 0; p < 8; p++) {
            const int4 o = off_s[wid][half * 8 + p];
            v[p][0] = __ldg((const float*)(gbase + o.x));
            v[p][1] = __ldg((const float*)(gbase + o.y));
            v[p][2] = __ldg((const float*)(gbase + o.z));
            v[p][3] = __ldg((const float*)(gbase + o.w));
        }

        #pragma unroll
        for (int p = 0; p < 8; p++) {
            const float4 c = cf_s[wid][half * 8 + p];
            acc0 = fmaf(c.x, v[p][0], acc0);
            acc1 = fmaf(c.y, v[p][1], acc1);
            acc0 = fmaf(c.z, v[p][2], acc0);
            acc1 = fmaf(c.w, v[p][3], acc1);
        }
    }

    // one contiguous 128B store per warp
    out[(size_t)u * MSDA_D + lane] = acc0 + acc1;
}

extern "C" void kernel_launch(void* const* d_in, const int* in_sizes, int n_in,
                              void* d_out, int out_size)
{
    const float* value = (const float*)d_in[0];
    const float* locp  = (const float*)d_in[1];
    const float* aw    = (const float*)d_in[2];
    float* out = (float*)d_out;

    const int blocks = MSDA_UNITS / WARPS_PER_BLOCK;   // 7200, exact
    msda_kernel<<<blocks, 256>>>(value, locp, aw, out);
}

// round 16
// speedup vs baseline: 1.6998x; 1.3189x over previous
#include <cuda_runtime.h>
#include <cstdint>

// MultiScaleDeformableAttention (bs=8, nq=900, nh=8, d=32, nl=4, npt=4)
// value: (8,22223,8,32) f32 | loc: (8,900,8,4,4,2) f32 | aw: (8,900,8,4,4) f32
// out: (8,900,256) f32
//
// R10 = R6 geometry (4 units/warp, LDG.128, prep split into smem) plus:
//  - rolling distance-2 software pipeline over points: consume p while p+1
//    is in flight, immediately reload the slot with p+2 (no memory drain)
//  - corner coeffs prefetched into regs at load time (no LDS on crit path)
//  - levels 0/1 (points 0..7) loaded with __ldcg (L2-only; don't evict the
//    level-2/3 slabs, which fit in L1), levels 2/3 with __ldg (L1-cached)

#define MSDA_NQ   900
#define MSDA_NH   8
#define MSDA_D    32
#define MSDA_KEYS 22223
#define MSDA_UNITS (8 * MSDA_NQ * MSDA_NH)   // 57600
#define UPB 32                               // units per block
#define PADU 33

typedef unsigned long long u64t;

__device__ __forceinline__ u64t pk2(float a) {
    u64t r; asm("mov.b64 %0, {%1, %1};" : "=l"(r) : "f"(a)); return r;
}
__device__ __forceinline__ void fma2(u64t& d, u64t a, u64t b) {
    asm("fma.rn.f32x2 %0, %1, %2, %0;" : "+l"(d) : "l"(a), "l"(b));
}
__device__ __forceinline__ void add2(u64t& d, u64t a) {
    asm("add.rn.f32x2 %0, %0, %1;" : "+l"(d) : "l"(a));
}

// Prep one point: absolute byte offsets (incl. level start) + corner coeffs.
__device__ __forceinline__ void prep_point(
    float lx, float ly, float w, int Wd, int Hd, int start_bytes,
    int4* __restrict__ op, float4* __restrict__ cp)
{
    const float x = fmaf(lx, (float)Wd, -0.5f);
    const float y = fmaf(ly, (float)Hd, -0.5f);
    const int x0 = __float2int_rd(x);
    const int y0 = __float2int_rd(y);
    const float wx1 = x - (float)x0, wy1 = y - (float)y0;
    const float wx0 = 1.0f - wx1,    wy0 = 1.0f - wy1;

    const bool vx0 = (unsigned)x0       < (unsigned)Wd;
    const bool vx1 = (unsigned)(x0 + 1) < (unsigned)Wd;
    const bool vy0 = (unsigned)y0       < (unsigned)Hd;
    const bool vy1 = (unsigned)(y0 + 1) < (unsigned)Hd;

    const int x0c = min(max(x0, 0), Wd - 1);
    const int x1c = min(max(x0 + 1, 0), Wd - 1);
    const int y0c = min(max(y0, 0), Hd - 1);
    const int y1c = min(max(y0 + 1, 0), Hd - 1);

    const int r0 = y0c * Wd, r1 = y1c * Wd;
    *op = make_int4(start_bytes + ((r0 + x0c) << 10),
                    start_bytes + ((r0 + x1c) << 10),
                    start_bytes + ((r1 + x0c) << 10),
                    start_bytes + ((r1 + x1c) << 10));

    const float wwy0 = w * wy0, wwy1 = w * wy1;
    *cp = make_float4(vx0 && vy0 ? wx0 * wwy0 : 0.0f,
                      vx1 && vy0 ? wx1 * wwy0 : 0.0f,
                      vx0 && vy1 ? wx0 * wwy1 : 0.0f,
                      vx1 && vy1 ? wx1 * wwy1 : 0.0f);
}

__global__ __launch_bounds__(256, 4) void msda_kernel(
    const float* __restrict__ value,
    const float* __restrict__ loc,
    const float* __restrict__ aw,
    float* __restrict__ out)
{
    __shared__ int4   off_s[16][PADU];
    __shared__ float4 cf_s [16][PADU];

    const int tid = threadIdx.x;
    const int u0  = blockIdx.x * UPB;
    const int lu  = tid >> 3;       // local unit 0..31
    const int j   = tid & 7;        // lane within unit

    // ---- Phase 1: lane j preps points 2j, 2j+1 of its unit ----
    {
        const float4 l2 = __ldg((const float4*)loc + (size_t)u0 * 8 + tid);
        const float2 w2 = __ldg((const float2*)aw  + (size_t)u0 * 8 + tid);

        const int lvl = j >> 1;
        const int Wd = lvl == 0 ? 167 : lvl == 1 ? 84 : lvl == 2 ? 42 : 21;
        const int Hd = lvl == 0 ? 100 : lvl == 1 ? 50 : lvl == 2 ? 25 : 13;
        const int sb = lvl == 0 ? 0
                     : lvl == 1 ? 16700 * 1024
                     : lvl == 2 ? 20900 * 1024
                     :            21950 * 1024;

        prep_point(l2.x, l2.y, w2.x, Wd, Hd, sb,
                   &off_s[2 * j][lu],     &cf_s[2 * j][lu]);
        prep_point(l2.z, l2.w, w2.y, Wd, Hd, sb,
                   &off_s[2 * j + 1][lu], &cf_s[2 * j + 1][lu]);
    }
    __syncwarp();   // unit lu's producers (tid lu*8+j) == consumers, same warp

    // ---- Phase 2: rolling distance-2 pipelined gather ----
    const int u = u0 + lu;
    const int h = u & 7;
    const int b = u / (MSDA_NQ * MSDA_NH);

    const char* __restrict__ gbase = (const char*)
        (value + (size_t)b * (MSDA_KEYS * 256) + h * MSDA_D + (j << 2));

    ulonglong2 s[2][4];     // two point-slots, 4 corners each (32 regs)
    float4     cf[2];       // prefetched corner coeffs

    // accumulate even points into (a0,a1), odd into (b0,b1)
    u64t a0 = 0, a1 = 0, b0 = 0, b1 = 0;

    // load point p into slot: levels 0/1 (p<8) L2-only, levels 2/3 L1-cached
    #define LOADPT(p, slot)                                                   \
        do {                                                                  \
            const int4 _o = off_s[p][lu];                                     \
            if ((p) < 8) {                                                    \
                s[slot][0] = __ldcg((const ulonglong2*)(gbase + _o.x));       \
                s[slot][1] = __ldcg((const ulonglong2*)(gbase + _o.y));       \
                s[slot][2] = __ldcg((const ulonglong2*)(gbase + _o.z));       \
                s[slot][3] = __ldcg((const ulonglong2*)(gbase + _o.w));       \
            } else {                                                          \
                s[slot][0] = __ldg((const ulonglong2*)(gbase + _o.x));        \
                s[slot][1] = __ldg((const ulonglong2*)(gbase + _o.y));        \
                s[slot][2] = __ldg((const ulonglong2*)(gbase + _o.z));        \
                s[slot][3] = __ldg((const ulonglong2*)(gbase + _o.w));        \
            }                                                                 \
            cf[slot] = cf_s[p][lu];                                           \
        } while (0)

    #define CONSUME(slot, x0r, x1r)                                           \
        do {                                                                  \
            const u64t _p0 = pk2(cf[slot].x), _p1 = pk2(cf[slot].y);          \
            const u64t _p2 = pk2(cf[slot].z), _p3 = pk2(cf[slot].w);          \
            fma2(x0r, _p0, s[slot][0].x);  fma2(x1r, _p0, s[slot][0].y);      \
            fma2(x0r, _p1, s[slot][1].x);  fma2(x1r, _p1, s[slot][1].y);      \
            fma2(x0r, _p2, s[slot][2].x);  fma2(x1r, _p2, s[slot][2].y);      \
            fma2(x0r, _p3, s[slot][3].x);  fma2(x1r, _p3, s[slot][3].y);      \
        } while (0)

    LOADPT(0, 0);
    LOADPT(1, 1);

    #pragma unroll
    for (int p = 0; p < 16; p++) {
        if (p & 1) {
            CONSUME(1, b0, b1);
            if (p + 2 < 16) LOADPT(p + 2, 1);
        } else {
            CONSUME(0, a0, a1);
            if (p + 2 < 16) LOADPT(p + 2, 0);
        }
    }

    #undef LOADPT
    #undef CONSUME

    add2(a0, b0);
    add2(a1, b1);

    float f0, f1, f2, f3;
    asm("mov.b64 {%0, %1}, %2;" : "=f"(f0), "=f"(f1) : "l"(a0));
    asm("mov.b64 {%0, %1}, %2;" : "=f"(f2), "=f"(f3) : "l"(a1));
    *(float4*)(out + (size_t)u * MSDA_D + (j << 2)) = make_float4(f0, f1, f2, f3);
}

extern "C" void kernel_launch(void* const* d_in, const int* in_sizes, int n_in,
                              void* d_out, int out_size)
{
    const float* value = (const float*)d_in[0];
    const float* locp  = (const float*)d_in[1];
    const float* aw    = (const float*)d_in[2];
    float* out = (float*)d_out;

    const int blocks = MSDA_UNITS / UPB;   // 1800, exact
    msda_kernel<<<blocks, 256>>>(value, locp, aw, out);
}